// round 13
// baseline (speedup 1.0000x reference)
#include <cuda_runtime.h>
#include <cuda_bf16.h>
#include <cstdint>

// Problem constants (fixed by the dataset)
#define SDIM 2048   // tokens per group
#define MDIM 768    // hidden size
#define HDIM 3072   // intermediate size
#define NEXP 16     // num experts
#define CAP  256    // capacity = 2*S/E
#define GMAX 2      // groups (4*1024 tokens / 2048)
#define KSPLIT 4    // split-K factor for GEMM2 (3072/4 = 768 per slice)

// ---------------- scratch (device globals; no runtime allocation) -----------
__device__ __align__(128) float g_disp[NEXP * GMAX * CAP * MDIM];   // [E][G][C][M]
__device__ __align__(128) float g_h   [NEXP * GMAX * CAP * HDIM];   // [E][G][C][H]
__device__ __align__(128) float g_eoP [KSPLIT * NEXP * GMAX * CAP * MDIM]; // [S][E][G][C][M]
__device__ int   g_e1  [GMAX * SDIM];
__device__ int   g_e2  [GMAX * SDIM];
__device__ int   g_pos1[GMAX * SDIM];                // -1 => dropped
__device__ int   g_pos2[GMAX * SDIM];
__device__ float g_gv1 [GMAX * SDIM];
__device__ float g_gv2 [GMAX * SDIM];
__device__ float g_w1  [GMAX * SDIM];
__device__ float g_w2  [GMAX * SDIM];
__device__ int   g_work;          // persistent-GEMM tile queue head
__device__ int   g_done[NEXP];    // per-expert completed gemm1 tiles

// ---------------- cp.async helpers (sm_80+; exonerated by R6 bisect) ---------
__device__ __forceinline__ uint32_t smem_u32(const void* p) {
    uint32_t a;
    asm("{ .reg .u64 t; cvta.to.shared.u64 t, %1; cvt.u32.u64 %0, t; }" : "=r"(a) : "l"(p));
    return a;
}
__device__ __forceinline__ void cp_async16(uint32_t s, const void* g) {
    asm volatile("cp.async.cg.shared.global [%0], [%1], 16;" :: "r"(s), "l"(g) : "memory");
}
__device__ __forceinline__ void cp_commit() {
    asm volatile("cp.async.commit_group;" ::: "memory");
}
template<int N>
__device__ __forceinline__ void cp_wait() {
    asm volatile("cp.async.wait_group %0;" :: "n"(N) : "memory");
}

// ---------------- 1) gating: softmax(x @ wg), top-2 -------------------------
__global__ void gating_kernel(const float* __restrict__ x,
                              const float* __restrict__ wg, int T) {
    int warp = (blockIdx.x * blockDim.x + threadIdx.x) >> 5;
    int lane = threadIdx.x & 31;
    if (warp >= T) return;
    const float* xr = x + (size_t)warp * MDIM;
    float acc[NEXP];
#pragma unroll
    for (int e = 0; e < NEXP; e++) acc[e] = 0.f;
    for (int k = lane; k < MDIM; k += 32) {
        float xv = xr[k];
        const float* w = wg + k * NEXP;
#pragma unroll
        for (int e = 0; e < NEXP; e++) acc[e] += xv * w[e];
    }
#pragma unroll
    for (int e = 0; e < NEXP; e++) {
#pragma unroll
        for (int off = 16; off; off >>= 1)
            acc[e] += __shfl_xor_sync(0xffffffffu, acc[e], off);
    }
    if (lane == 0) {
        float mx = acc[0];
#pragma unroll
        for (int e = 1; e < NEXP; e++) mx = fmaxf(mx, acc[e]);
        float p[NEXP], sum = 0.f;
#pragma unroll
        for (int e = 0; e < NEXP; e++) { p[e] = expf(acc[e] - mx); sum += p[e]; }
        float inv = 1.f / sum;
        int e1 = 0; float b1 = p[0];
#pragma unroll
        for (int e = 1; e < NEXP; e++) if (p[e] > b1) { b1 = p[e]; e1 = e; }
        int e2 = 0; float b2 = -1.f;
#pragma unroll
        for (int e = 0; e < NEXP; e++)
            if (e != e1 && p[e] > b2) { b2 = p[e]; e2 = e; }
        g_e1[warp] = e1; g_e2[warp] = e2;
        g_gv1[warp] = b1 * inv; g_gv2[warp] = b2 * inv;
    }
}

// ---------------- 2) capacity scan per group (SMEM-staged) + queue reset -----
__global__ void scan_kernel(int G) {
    __shared__ int se1[SDIM];
    __shared__ int se2[SDIM];
    __shared__ int s_cnt1[NEXP];
    int g = blockIdx.x;
    int tid = threadIdx.x;
    int base = g * SDIM;
    if (g == 0) {                      // reset persistent-GEMM queue each launch
        if (tid == 0) g_work = 0;
        if (tid < NEXP) g_done[tid] = 0;
    }
    for (int s = tid; s < SDIM; s += blockDim.x) {
        se1[s] = g_e1[base + s];
        se2[s] = g_e2[base + s];
    }
    __syncthreads();
    if (tid < NEXP) {
        int cnt = 0;
        for (int s = 0; s < SDIM; s++) {
            if (se1[s] == tid) {
                int p = cnt++;
                g_pos1[base + s] = (p < CAP) ? p : -1;
            }
        }
        s_cnt1[tid] = cnt < CAP ? cnt : CAP;
    }
    __syncthreads();
    if (tid < NEXP) {
        int cnt = 0, off = s_cnt1[tid];
        for (int s = 0; s < SDIM; s++) {
            if (se2[s] == tid) {
                int p = cnt++ + off;
                g_pos2[base + s] = (p < CAP) ? p : -1;
            }
        }
    }
    __syncthreads();
    for (int s = tid; s < SDIM; s += blockDim.x) {
        int t = base + s;
        float a = (g_pos1[t] >= 0) ? g_gv1[t] : 0.f;
        float b = (g_pos2[t] >= 0) ? g_gv2[t] : 0.f;
        float den = a + b;
        den = (den > 0.f) ? den : 1.f;
        g_w1[t] = a / den;
        g_w2[t] = b / den;
    }
}

// ---------------- 3) scatter tokens into dispatch buffer (float4) ------------
__global__ void scatter_kernel(const float* __restrict__ x, int G) {
    int t = blockIdx.x;
    int g = t / SDIM;
    const float4* xr = (const float4*)(x + (size_t)t * MDIM);
    int p1 = g_pos1[t], p2 = g_pos2[t];
    float4* d1 = (p1 >= 0) ? (float4*)(g_disp + (((size_t)g_e1[t] * G + g) * CAP + p1) * MDIM) : nullptr;
    float4* d2 = (p2 >= 0) ? (float4*)(g_disp + (((size_t)g_e2[t] * G + g) * CAP + p2) * MDIM) : nullptr;
    int m = threadIdx.x;            // 192 threads = 192 float4 = 768 floats
    float4 v = xr[m];
    if (d1) d1[m] = v;
    if (d2) d2[m] = v;
}

// ---------------- SGEMM tile body: 3-stage cp.async pipeline -----------------
// 128x128 tile, K-chunk 16; one sync per chunk; zero staging registers.
__device__ void sgemm_tile(
    const float* __restrict__ A, const float* __restrict__ B, float* __restrict__ C,
    int K, int lda, int ldb, int ldc, bool relu, int bx, int by,
    float (*As)[16][128], float (*Bs)[16][128]) {
    const int tid = threadIdx.x;
    const int arow = tid >> 1, acol = (tid & 1) * 8;   // A loader: 128 rows x 16 k
    const int brow = tid >> 4, bcol = (tid & 15) * 8;  // B loader: 16 k x 128 cols
    const int tx = tid & 15, ty = tid >> 4;            // 16x16 compute threads

    A += (size_t)by * 128 * lda;
    B += (size_t)bx * 128;
    C += (size_t)by * 128 * ldc + (size_t)bx * 128;

    const float* Arow = A + (size_t)arow * lda + acol;
    const float* Brow0 = B + (size_t)brow * ldb + bcol;

    // smem byte addresses for this thread's two 16B/32B destinations per stage
    uint32_t sA[3], sB[3];
#pragma unroll
    for (int s = 0; s < 3; s++) {
        sA[s] = smem_u32(&As[s][0][0]) + (uint32_t)(acol * 128 + arow) * 4; // col-major As[k][row]
        sB[s] = smem_u32(&Bs[s][brow][bcol]);
    }

    const int nT = K / 16;

    // A is stored transposed (As[k][row]); cp.async is linear, so A must be
    // copied as 8 separate 4B words? No — keep A in SMEM as [k][128] but load
    // via cp.async in B-style rows: instead copy A K-major per-thread 16B into
    // a [row][16] layout and transpose at fragment time would break the proven
    // fragment path. Solution: stage A through cp.async into an auxiliary
    // row-major layout is wrong; instead we cp.async A as 4B x8? Too slow.
    // => Use 16B cp.async into [k][row] by having each thread own ONE k-column
    //    segment: thread loads A[row][k..k+7] which maps to 8 DIFFERENT smem
    //    rows — not contiguous. Therefore A uses a [row][16] SMEM tile and the
    //    fragment loader reads strided (conflict-free: stride 16 floats = bank
    //    cycle 16, 2-way conflict). Accepted: A fragment loads are broadcast
    //    (2 addresses/warp) so conflicts don't apply.
    (void)sA;

    // --- actual implementation: A staged row-major As_r[row][16] ---
    // reuse As storage as [stage][128][16] row-major
    float* AsR[3];
#pragma unroll
    for (int s = 0; s < 3; s++) AsR[s] = &As[s][0][0];
    uint32_t sAr[3];
#pragma unroll
    for (int s = 0; s < 3; s++)
        sAr[s] = smem_u32(AsR[s]) + (uint32_t)(arow * 16 + acol) * 4;

    // prologue: chunks 0 and 1
#pragma unroll
    for (int s = 0; s < 2; s++) {
        cp_async16(sAr[s], Arow + s * 16);
        cp_async16(sAr[s] + 16, Arow + s * 16 + 4);
        cp_async16(sB[s], Brow0 + (size_t)s * 16 * ldb);
        cp_async16(sB[s] + 16, Brow0 + (size_t)s * 16 * ldb + 4);
        cp_commit();
    }

    float acc[8][8];
#pragma unroll
    for (int i = 0; i < 8; i++)
#pragma unroll
        for (int j = 0; j < 8; j++) acc[i][j] = 0.f;

    for (int t = 0; t < nT; t++) {
        if (t < nT - 1) cp_wait<1>(); else cp_wait<0>();
        __syncthreads();

        // prefetch chunk t+2 into the free stage
        if (t + 2 < nT) {
            const int sp = (t + 2) % 3;
            cp_async16(sAr[sp], Arow + (t + 2) * 16);
            cp_async16(sAr[sp] + 16, Arow + (t + 2) * 16 + 4);
            cp_async16(sB[sp], Brow0 + (size_t)(t + 2) * 16 * ldb);
            cp_async16(sB[sp] + 16, Brow0 + (size_t)(t + 2) * 16 * ldb + 4);
            cp_commit();
        }

        const int s = t % 3;
        const float* Ar = AsR[s];     // row-major [128][16]
#pragma unroll
        for (int k = 0; k < 16; k++) {
            float ar[8], br[8];
            // A fragment: rows ty*4..+3 and 64+ty*4..+3 at column k.
            // Strided (stride 16 floats) but warp-broadcast (8 distinct addrs).
#pragma unroll
            for (int i = 0; i < 4; i++) ar[i] = Ar[(ty * 4 + i) * 16 + k];
#pragma unroll
            for (int i = 0; i < 4; i++) ar[4 + i] = Ar[(64 + ty * 4 + i) * 16 + k];
            *(float4*)&br[0] = *(const float4*)&Bs[s][k][tx * 4];
            *(float4*)&br[4] = *(const float4*)&Bs[s][k][64 + tx * 4];
#pragma unroll
            for (int i = 0; i < 8; i++)
#pragma unroll
                for (int j = 0; j < 8; j++) acc[i][j] += ar[i] * br[j];
        }
        __syncthreads();
    }

    // epilogue: rows ty*4+i (+64), col groups tx*4 (+64); float4 stores
#pragma unroll
    for (int ih = 0; ih < 2; ih++) {
#pragma unroll
        for (int i = 0; i < 4; i++) {
            int row = ih * 64 + ty * 4 + i;
            float* cr = C + (size_t)row * ldc;
#pragma unroll
            for (int jh = 0; jh < 2; jh++) {
                float4 v;
                v.x = acc[ih * 4 + i][jh * 4 + 0];
                v.y = acc[ih * 4 + i][jh * 4 + 1];
                v.z = acc[ih * 4 + i][jh * 4 + 2];
                v.w = acc[ih * 4 + i][jh * 4 + 3];
                if (relu) {
                    v.x = fmaxf(v.x, 0.f); v.y = fmaxf(v.y, 0.f);
                    v.z = fmaxf(v.z, 0.f); v.w = fmaxf(v.w, 0.f);
                }
                *(float4*)(cr + jh * 64 + tx * 4) = v;
            }
        }
    }
}

// ---------------- 4+5) persistent fused GEMM (work queue + expert gating) ----
__global__ __launch_bounds__(256, 2) void moe_gemm_fused(
    const float* __restrict__ wi, const float* __restrict__ wo, int G)
{
    __shared__ float As[3][16][128];   // 24 KB (A staged row-major inside)
    __shared__ float Bs[3][16][128];   // 24 KB
    __shared__ int s_id;
    const int Mr = G * CAP;                         // 512
    const int mT = Mr / 128;                        // 4
    const int t1_per_e = (HDIM / 128) * mT;         // 96
    const int nT1 = NEXP * t1_per_e;                // 1536
    const int t2_per_s = (MDIM / 128) * mT;         // 24
    const int t2_per_e = KSPLIT * t2_per_s;         // 96
    const int nAll = nT1 + NEXP * t2_per_e;         // 3072

    for (;;) {
        if (threadIdx.x == 0) s_id = atomicAdd(&g_work, 1);
        __syncthreads();
        int id = s_id;
        __syncthreads();
        if (id >= nAll) break;

        if (id < nT1) {
            // GEMM1 tile: h[e] = relu(disp[e] @ wi[e])
            int e = id / t1_per_e, r = id % t1_per_e;
            int n = r / mT, m = r % mT;
            const float* A = g_disp + (size_t)e * Mr * MDIM;
            const float* B = wi + (size_t)e * MDIM * HDIM;
            float* C = g_h + (size_t)e * Mr * HDIM;
            sgemm_tile(A, B, C, MDIM, MDIM, HDIM, HDIM, true, n, m, As, Bs);
            __syncthreads();
            if (threadIdx.x == 0) { __threadfence(); atomicAdd(&g_done[e], 1); }
        } else {
            // GEMM2 tile (split-K): gated on expert e's gemm1 completion
            int id2 = id - nT1;
            int e = id2 / t2_per_e, r = id2 % t2_per_e;
            int s = r / t2_per_s, r2 = r % t2_per_s;
            int n = r2 / mT, m = r2 % mT;
            if (threadIdx.x == 0) {
                while (*(volatile int*)&g_done[e] < t1_per_e) __nanosleep(64);
            }
            __syncthreads();
            __threadfence();   // acquire: order g_h reads after observed flag
            const int KS = HDIM / KSPLIT;          // 768 per slice
            const float* A = g_h + (size_t)e * Mr * HDIM + (size_t)s * KS;
            const float* B = wo + (size_t)e * HDIM * MDIM + (size_t)s * KS * MDIM;
            float* C = g_eoP + ((size_t)s * NEXP + e) * Mr * MDIM;
            sgemm_tile(A, B, C, KS, HDIM, MDIM, MDIM, false, n, m, As, Bs);
            __syncthreads();
        }
    }
}

// ---------------- 6) combine (sums split-K partials, float4) -----------------
__global__ void combine_kernel(float* __restrict__ out, int G) {
    int t = blockIdx.x;
    int g = t / SDIM;
    int p1 = g_pos1[t], p2 = g_pos2[t];
    float w1 = g_w1[t], w2 = g_w2[t];
    const size_t sliceStride4 = (size_t)NEXP * G * CAP * MDIM / 4;
    const float4* r1 = (p1 >= 0)
        ? (const float4*)(g_eoP + (((size_t)g_e1[t] * G + g) * CAP + p1) * MDIM) : nullptr;
    const float4* r2 = (p2 >= 0)
        ? (const float4*)(g_eoP + (((size_t)g_e2[t] * G + g) * CAP + p2) * MDIM) : nullptr;
    float4* o = (float4*)(out + (size_t)t * MDIM);
    int m = threadIdx.x;            // 192 threads = 768 floats
    float4 v; v.x = v.y = v.z = v.w = 0.f;
    if (r1) {
        float4 s1; s1.x = s1.y = s1.z = s1.w = 0.f;
#pragma unroll
        for (int s = 0; s < KSPLIT; s++) {
            float4 p = r1[s * sliceStride4 + m];
            s1.x += p.x; s1.y += p.y; s1.z += p.z; s1.w += p.w;
        }
        v.x += w1 * s1.x; v.y += w1 * s1.y; v.z += w1 * s1.z; v.w += w1 * s1.w;
    }
    if (r2) {
        float4 s2; s2.x = s2.y = s2.z = s2.w = 0.f;
#pragma unroll
        for (int s = 0; s < KSPLIT; s++) {
            float4 p = r2[s * sliceStride4 + m];
            s2.x += p.x; s2.y += p.y; s2.z += p.z; s2.w += p.w;
        }
        v.x += w2 * s2.x; v.y += w2 * s2.y; v.z += w2 * s2.z; v.w += w2 * s2.w;
    }
    o[m] = v;
}

// ---------------- launcher --------------------------------------------------
extern "C" void kernel_launch(void* const* d_in, const int* in_sizes, int n_in,
                              void* d_out, int out_size) {
    const float* x  = (const float*)d_in[0];   // [4,1024,768] fp32
    const float* wg = (const float*)d_in[1];   // [768,16]
    const float* wi = (const float*)d_in[2];   // [16,768,3072]
    const float* wo = (const float*)d_in[3];   // [16,3072,768]
    float* out = (float*)d_out;

    int T = in_sizes[0] / MDIM;   // 4096 tokens
    int G = T / SDIM;             // 2 groups
    if (G > GMAX) G = GMAX;

    int dev = 0, sms = 148;
    cudaGetDevice(&dev);
    cudaDeviceGetAttribute(&sms, cudaDevAttrMultiProcessorCount, dev);

    gating_kernel<<<(T + 3) / 4, 128>>>(x, wg, T);
    scan_kernel<<<G, 256>>>(G);
    scatter_kernel<<<T, 192>>>(x, G);
    moe_gemm_fused<<<2 * sms, 256>>>(wi, wo, G);
    combine_kernel<<<T, 192>>>(out, G);
}

// round 14
// speedup vs baseline: 1.1120x; 1.1120x over previous
#include <cuda_runtime.h>
#include <cuda_bf16.h>
#include <cstdint>

// Problem constants (fixed by the dataset)
#define SDIM 2048   // tokens per group
#define MDIM 768    // hidden size
#define HDIM 3072   // intermediate size
#define NEXP 16     // num experts
#define CAP  256    // capacity = 2*S/E
#define GMAX 2      // groups (4*1024 tokens / 2048)
#define KSPLIT 4    // split-K factor for GEMM2 (3072/4 = 768 per slice)
#define KC   32     // GEMM K-chunk

// ---------------- scratch (device globals; no runtime allocation) -----------
__device__ __align__(128) float g_disp[NEXP * GMAX * CAP * MDIM];   // [E][G][C][M]
__device__ __align__(128) float g_h   [NEXP * GMAX * CAP * HDIM];   // [E][G][C][H]
__device__ __align__(128) float g_eoP [KSPLIT * NEXP * GMAX * CAP * MDIM]; // [S][E][G][C][M]
__device__ int   g_e1  [GMAX * SDIM];
__device__ int   g_e2  [GMAX * SDIM];
__device__ int   g_pos1[GMAX * SDIM];                // -1 => dropped
__device__ int   g_pos2[GMAX * SDIM];
__device__ float g_gv1 [GMAX * SDIM];
__device__ float g_gv2 [GMAX * SDIM];
__device__ float g_w1  [GMAX * SDIM];
__device__ float g_w2  [GMAX * SDIM];
__device__ int   g_work;          // persistent-GEMM tile queue head
__device__ int   g_done[NEXP];    // per-expert completed gemm1 tiles

// ---------------- cp.async helpers ------------------------------------------
__device__ __forceinline__ uint32_t smem_u32(const void* p) {
    uint32_t a;
    asm("{ .reg .u64 t; cvta.to.shared.u64 t, %1; cvt.u32.u64 %0, t; }" : "=r"(a) : "l"(p));
    return a;
}
__device__ __forceinline__ void cp_async16(uint32_t s, const void* g) {
    asm volatile("cp.async.cg.shared.global [%0], [%1], 16;" :: "r"(s), "l"(g) : "memory");
}
__device__ __forceinline__ void cp_commit() {
    asm volatile("cp.async.commit_group;" ::: "memory");
}
template<int N>
__device__ __forceinline__ void cp_wait() {
    asm volatile("cp.async.wait_group %0;" :: "n"(N) : "memory");
}

// ---------------- 1) gating: softmax(x @ wg), top-2 -------------------------
__global__ void gating_kernel(const float* __restrict__ x,
                              const float* __restrict__ wg, int T) {
    int warp = (blockIdx.x * blockDim.x + threadIdx.x) >> 5;
    int lane = threadIdx.x & 31;
    if (warp >= T) return;
    const float* xr = x + (size_t)warp * MDIM;
    float acc[NEXP];
#pragma unroll
    for (int e = 0; e < NEXP; e++) acc[e] = 0.f;
    for (int k = lane; k < MDIM; k += 32) {
        float xv = xr[k];
        const float* w = wg + k * NEXP;
#pragma unroll
        for (int e = 0; e < NEXP; e++) acc[e] += xv * w[e];
    }
#pragma unroll
    for (int e = 0; e < NEXP; e++) {
#pragma unroll
        for (int off = 16; off; off >>= 1)
            acc[e] += __shfl_xor_sync(0xffffffffu, acc[e], off);
    }
    if (lane == 0) {
        float mx = acc[0];
#pragma unroll
        for (int e = 1; e < NEXP; e++) mx = fmaxf(mx, acc[e]);
        float p[NEXP], sum = 0.f;
#pragma unroll
        for (int e = 0; e < NEXP; e++) { p[e] = expf(acc[e] - mx); sum += p[e]; }
        float inv = 1.f / sum;
        int e1 = 0; float b1 = p[0];
#pragma unroll
        for (int e = 1; e < NEXP; e++) if (p[e] > b1) { b1 = p[e]; e1 = e; }
        int e2 = 0; float b2 = -1.f;
#pragma unroll
        for (int e = 0; e < NEXP; e++)
            if (e != e1 && p[e] > b2) { b2 = p[e]; e2 = e; }
        g_e1[warp] = e1; g_e2[warp] = e2;
        g_gv1[warp] = b1 * inv; g_gv2[warp] = b2 * inv;
    }
}

// ---------------- 2) capacity scan per group (SMEM-staged) + queue reset -----
__global__ void scan_kernel(int G) {
    __shared__ int se1[SDIM];
    __shared__ int se2[SDIM];
    __shared__ int s_cnt1[NEXP];
    int g = blockIdx.x;
    int tid = threadIdx.x;
    int base = g * SDIM;
    if (g == 0) {                      // reset persistent-GEMM queue each launch
        if (tid == 0) g_work = 0;
        if (tid < NEXP) g_done[tid] = 0;
    }
    for (int s = tid; s < SDIM; s += blockDim.x) {
        se1[s] = g_e1[base + s];
        se2[s] = g_e2[base + s];
    }
    __syncthreads();
    if (tid < NEXP) {
        int cnt = 0;
        for (int s = 0; s < SDIM; s++) {
            if (se1[s] == tid) {
                int p = cnt++;
                g_pos1[base + s] = (p < CAP) ? p : -1;
            }
        }
        s_cnt1[tid] = cnt < CAP ? cnt : CAP;
    }
    __syncthreads();
    if (tid < NEXP) {
        int cnt = 0, off = s_cnt1[tid];
        for (int s = 0; s < SDIM; s++) {
            if (se2[s] == tid) {
                int p = cnt++ + off;
                g_pos2[base + s] = (p < CAP) ? p : -1;
            }
        }
    }
    __syncthreads();
    for (int s = tid; s < SDIM; s += blockDim.x) {
        int t = base + s;
        float a = (g_pos1[t] >= 0) ? g_gv1[t] : 0.f;
        float b = (g_pos2[t] >= 0) ? g_gv2[t] : 0.f;
        float den = a + b;
        den = (den > 0.f) ? den : 1.f;
        g_w1[t] = a / den;
        g_w2[t] = b / den;
    }
}

// ---------------- 3) scatter tokens into dispatch buffer (float4) ------------
__global__ void scatter_kernel(const float* __restrict__ x, int G) {
    int t = blockIdx.x;
    int g = t / SDIM;
    const float4* xr = (const float4*)(x + (size_t)t * MDIM);
    int p1 = g_pos1[t], p2 = g_pos2[t];
    float4* d1 = (p1 >= 0) ? (float4*)(g_disp + (((size_t)g_e1[t] * G + g) * CAP + p1) * MDIM) : nullptr;
    float4* d2 = (p2 >= 0) ? (float4*)(g_disp + (((size_t)g_e2[t] * G + g) * CAP + p2) * MDIM) : nullptr;
    int m = threadIdx.x;            // 192 threads = 192 float4 = 768 floats
    float4 v = xr[m];
    if (d1) d1[m] = v;
    if (d2) d2[m] = v;
}

// ---------------- SGEMM tile body: K-chunk 32, A reg-staged, B cp.async ------
// A SMEM layout transposed [k][128] (R12-proven fragment path); B SMEM layout
// [k][128] == B's global row layout, so cp.async copies it directly.
__device__ void sgemm_tile(
    const float* __restrict__ A, const float* __restrict__ B, float* __restrict__ C,
    int K, int lda, int ldb, int ldc, bool relu, int bx, int by,
    float* AsRaw, float* BsRaw) {
    const int tid = threadIdx.x;
    const int arow = tid >> 1, acol0 = (tid & 1) * 16;  // A loader: 128 rows x 32 k
    const int tx = tid & 15, ty = tid >> 4;             // 16x16 compute threads

    A += (size_t)by * 128 * lda;
    B += (size_t)bx * 128;
    C += (size_t)by * 128 * ldc + (size_t)bx * 128;

    const float* Arow = A + (size_t)arow * lda + acol0;

    // stage pointers: As[s][k][128], Bs[s][k][128]
    float* As[2] = { AsRaw, AsRaw + KC * 128 };
    float* Bs[2] = { BsRaw, BsRaw + KC * 128 };
    // B cp.async mapping: 4 chunks of 16B per thread cover 32 rows x 512B
    const int bIdx0 = tid;                  // float4 index base; +256 per j
    uint32_t sBdst[2][4];
    const float* bSrc[4];
#pragma unroll
    for (int j = 0; j < 4; j++) {
        int idx = bIdx0 + j * 256;          // 0..1023 float4s
        int row = idx >> 5;                 // 0..31
        int c4  = idx & 31;                 // float4 within row
        sBdst[0][j] = smem_u32(Bs[0] + row * 128 + c4 * 4);
        sBdst[1][j] = smem_u32(Bs[1] + row * 128 + c4 * 4);
        bSrc[j] = B + (size_t)row * ldb + c4 * 4;
    }

    const int nT = K / KC;

    float4 a0, a1, a2, a3;

    // prologue: chunk 0 -> stage 0
    a0 = *(const float4*)(Arow);
    a1 = *(const float4*)(Arow + 4);
    a2 = *(const float4*)(Arow + 8);
    a3 = *(const float4*)(Arow + 12);
    {
        const float av[16] = { a0.x,a0.y,a0.z,a0.w, a1.x,a1.y,a1.z,a1.w,
                               a2.x,a2.y,a2.z,a2.w, a3.x,a3.y,a3.z,a3.w };
#pragma unroll
        for (int j = 0; j < 16; j++) As[0][(acol0 + j) * 128 + arow] = av[j];
#pragma unroll
        for (int j = 0; j < 4; j++) cp_async16(sBdst[0][j], bSrc[j]);
        cp_commit();
    }
    cp_wait<0>();
    __syncthreads();

    float acc[8][8];
#pragma unroll
    for (int i = 0; i < 8; i++)
#pragma unroll
        for (int j = 0; j < 8; j++) acc[i][j] = 0.f;

    for (int t = 0; t < nT; t++) {
        const int s = t & 1;
        const int sn = s ^ 1;

        // issue next chunk's loads before compute (full-chunk latency cover)
        if (t + 1 < nT) {
            const float* An = Arow + (t + 1) * KC;
            a0 = *(const float4*)(An);
            a1 = *(const float4*)(An + 4);
            a2 = *(const float4*)(An + 8);
            a3 = *(const float4*)(An + 12);
#pragma unroll
            for (int j = 0; j < 4; j++)
                cp_async16(sBdst[sn][j], bSrc[j] + (size_t)(t + 1) * KC * ldb);
            cp_commit();
        }

        const float* Ask = As[s];
        const float* Bsk = Bs[s];
#pragma unroll
        for (int k = 0; k < KC; k++) {
            float ar[8], br[8];
            *(float4*)&ar[0] = *(const float4*)&Ask[k * 128 + ty * 4];
            *(float4*)&ar[4] = *(const float4*)&Ask[k * 128 + 64 + ty * 4];
            *(float4*)&br[0] = *(const float4*)&Bsk[k * 128 + tx * 4];
            *(float4*)&br[4] = *(const float4*)&Bsk[k * 128 + 64 + tx * 4];
#pragma unroll
            for (int i = 0; i < 8; i++)
#pragma unroll
                for (int j = 0; j < 8; j++) acc[i][j] += ar[i] * br[j];
        }

        if (t + 1 < nT) {
            const float av[16] = { a0.x,a0.y,a0.z,a0.w, a1.x,a1.y,a1.z,a1.w,
                                   a2.x,a2.y,a2.z,a2.w, a3.x,a3.y,a3.z,a3.w };
#pragma unroll
            for (int j = 0; j < 16; j++) As[sn][(acol0 + j) * 128 + arow] = av[j];
            cp_wait<0>();
        }
        __syncthreads();
    }

    // epilogue: rows ty*4+i (+64), col groups tx*4 (+64); float4 stores
#pragma unroll
    for (int ih = 0; ih < 2; ih++) {
#pragma unroll
        for (int i = 0; i < 4; i++) {
            int row = ih * 64 + ty * 4 + i;
            float* cr = C + (size_t)row * ldc;
#pragma unroll
            for (int jh = 0; jh < 2; jh++) {
                float4 v;
                v.x = acc[ih * 4 + i][jh * 4 + 0];
                v.y = acc[ih * 4 + i][jh * 4 + 1];
                v.z = acc[ih * 4 + i][jh * 4 + 2];
                v.w = acc[ih * 4 + i][jh * 4 + 3];
                if (relu) {
                    v.x = fmaxf(v.x, 0.f); v.y = fmaxf(v.y, 0.f);
                    v.z = fmaxf(v.z, 0.f); v.w = fmaxf(v.w, 0.f);
                }
                *(float4*)(cr + jh * 64 + tx * 4) = v;
            }
        }
    }
}

// ---------------- 4+5) persistent fused GEMM (work queue + expert gating) ----
__global__ __launch_bounds__(256, 2) void moe_gemm_fused(
    const float* __restrict__ wi, const float* __restrict__ wo, int G)
{
    extern __shared__ float dynsmem[];          // 2*KC*128 (A) + 2*KC*128 (B)
    float* AsRaw = dynsmem;                     // 32 KB
    float* BsRaw = dynsmem + 2 * KC * 128;      // 32 KB
    __shared__ int s_id;
    const int Mr = G * CAP;                         // 512
    const int mT = Mr / 128;                        // 4
    const int t1_per_e = (HDIM / 128) * mT;         // 96
    const int nT1 = NEXP * t1_per_e;                // 1536
    const int t2_per_s = (MDIM / 128) * mT;         // 24
    const int t2_per_e = KSPLIT * t2_per_s;         // 96
    const int nAll = nT1 + NEXP * t2_per_e;         // 3072

    for (;;) {
        if (threadIdx.x == 0) s_id = atomicAdd(&g_work, 1);
        __syncthreads();
        int id = s_id;
        __syncthreads();
        if (id >= nAll) break;

        if (id < nT1) {
            // GEMM1 tile: h[e] = relu(disp[e] @ wi[e])
            int e = id / t1_per_e, r = id % t1_per_e;
            int n = r / mT, m = r % mT;
            const float* A = g_disp + (size_t)e * Mr * MDIM;
            const float* B = wi + (size_t)e * MDIM * HDIM;
            float* C = g_h + (size_t)e * Mr * HDIM;
            sgemm_tile(A, B, C, MDIM, MDIM, HDIM, HDIM, true, n, m, AsRaw, BsRaw);
            __syncthreads();
            if (threadIdx.x == 0) { __threadfence(); atomicAdd(&g_done[e], 1); }
        } else {
            // GEMM2 tile (split-K): gated on expert e's gemm1 completion
            int id2 = id - nT1;
            int e = id2 / t2_per_e, r = id2 % t2_per_e;
            int s = r / t2_per_s, r2 = r % t2_per_s;
            int n = r2 / mT, m = r2 % mT;
            if (threadIdx.x == 0) {
                while (*(volatile int*)&g_done[e] < t1_per_e) __nanosleep(64);
            }
            __syncthreads();
            __threadfence();   // acquire: order g_h reads after observed flag
            const int KS = HDIM / KSPLIT;          // 768 per slice
            const float* A = g_h + (size_t)e * Mr * HDIM + (size_t)s * KS;
            const float* B = wo + (size_t)e * HDIM * MDIM + (size_t)s * KS * MDIM;
            float* C = g_eoP + ((size_t)s * NEXP + e) * Mr * MDIM;
            sgemm_tile(A, B, C, KS, HDIM, MDIM, MDIM, false, n, m, AsRaw, BsRaw);
            __syncthreads();
        }
    }
}

// ---------------- 6) combine (sums split-K partials, float4) -----------------
__global__ void combine_kernel(float* __restrict__ out, int G) {
    int t = blockIdx.x;
    int g = t / SDIM;
    int p1 = g_pos1[t], p2 = g_pos2[t];
    float w1 = g_w1[t], w2 = g_w2[t];
    const size_t sliceStride4 = (size_t)NEXP * G * CAP * MDIM / 4;
    const float4* r1 = (p1 >= 0)
        ? (const float4*)(g_eoP + (((size_t)g_e1[t] * G + g) * CAP + p1) * MDIM) : nullptr;
    const float4* r2 = (p2 >= 0)
        ? (const float4*)(g_eoP + (((size_t)g_e2[t] * G + g) * CAP + p2) * MDIM) : nullptr;
    float4* o = (float4*)(out + (size_t)t * MDIM);
    int m = threadIdx.x;            // 192 threads = 768 floats
    float4 v; v.x = v.y = v.z = v.w = 0.f;
    if (r1) {
        float4 s1; s1.x = s1.y = s1.z = s1.w = 0.f;
#pragma unroll
        for (int s = 0; s < KSPLIT; s++) {
            float4 p = r1[s * sliceStride4 + m];
            s1.x += p.x; s1.y += p.y; s1.z += p.z; s1.w += p.w;
        }
        v.x += w1 * s1.x; v.y += w1 * s1.y; v.z += w1 * s1.z; v.w += w1 * s1.w;
    }
    if (r2) {
        float4 s2; s2.x = s2.y = s2.z = s2.w = 0.f;
#pragma unroll
        for (int s = 0; s < KSPLIT; s++) {
            float4 p = r2[s * sliceStride4 + m];
            s2.x += p.x; s2.y += p.y; s2.z += p.z; s2.w += p.w;
        }
        v.x += w2 * s2.x; v.y += w2 * s2.y; v.z += w2 * s2.z; v.w += w2 * s2.w;
    }
    o[m] = v;
}

// ---------------- launcher --------------------------------------------------
extern "C" void kernel_launch(void* const* d_in, const int* in_sizes, int n_in,
                              void* d_out, int out_size) {
    const float* x  = (const float*)d_in[0];   // [4,1024,768] fp32
    const float* wg = (const float*)d_in[1];   // [768,16]
    const float* wi = (const float*)d_in[2];   // [16,768,3072]
    const float* wo = (const float*)d_in[3];   // [16,3072,768]
    float* out = (float*)d_out;

    int T = in_sizes[0] / MDIM;   // 4096 tokens
    int G = T / SDIM;             // 2 groups
    if (G > GMAX) G = GMAX;

    int dev = 0, sms = 148;
    cudaGetDevice(&dev);
    cudaDeviceGetAttribute(&sms, cudaDevAttrMultiProcessorCount, dev);

    const int smemBytes = 2 * KC * 128 * 2 * (int)sizeof(float);   // 64 KB
    cudaFuncSetAttribute(moe_gemm_fused,
                         cudaFuncAttributeMaxDynamicSharedMemorySize, smemBytes);

    gating_kernel<<<(T + 3) / 4, 128>>>(x, wg, T);
    scan_kernel<<<G, 256>>>(G);
    scatter_kernel<<<T, 192>>>(x, G);
    moe_gemm_fused<<<2 * sms, 256, smemBytes>>>(wi, wo, G);
    combine_kernel<<<T, 192>>>(out, G);
}

// round 15
// speedup vs baseline: 1.2349x; 1.1105x over previous
#include <cuda_runtime.h>
#include <cuda_bf16.h>
#include <cstdint>

// Problem constants (fixed by the dataset)
#define SDIM 2048   // tokens per group
#define MDIM 768    // hidden size
#define HDIM 3072   // intermediate size
#define NEXP 16     // num experts
#define CAP  256    // capacity = 2*S/E
#define GMAX 2      // groups (4*1024 tokens / 2048)
#define KSPLIT 4    // split-K factor for GEMM2 (3072/4 = 768 per slice)

// ---------------- scratch (device globals; no runtime allocation) -----------
__device__ __align__(128) float g_disp[NEXP * GMAX * CAP * MDIM];   // [E][G][C][M]
__device__ __align__(128) float g_h   [NEXP * GMAX * CAP * HDIM];   // [E][G][C][H]
__device__ __align__(128) float g_eoP [KSPLIT * NEXP * GMAX * CAP * MDIM]; // [S][E][G][C][M]
__device__ int   g_e1  [GMAX * SDIM];
__device__ int   g_e2  [GMAX * SDIM];
__device__ int   g_pos1[GMAX * SDIM];                // -1 => dropped
__device__ int   g_pos2[GMAX * SDIM];
__device__ float g_gv1 [GMAX * SDIM];
__device__ float g_gv2 [GMAX * SDIM];
__device__ float g_w1  [GMAX * SDIM];
__device__ float g_w2  [GMAX * SDIM];
__device__ int   g_work;          // persistent tile queue head
__device__ int   g_done[NEXP];    // per-expert completed gemm1 tiles
__device__ int   g_done2;         // completed gemm2 tiles (gates combine)

// ---------------- 1) gating: softmax(x @ wg), top-2 -------------------------
__global__ void gating_kernel(const float* __restrict__ x,
                              const float* __restrict__ wg, int T) {
    int warp = (blockIdx.x * blockDim.x + threadIdx.x) >> 5;
    int lane = threadIdx.x & 31;
    if (warp >= T) return;
    const float* xr = x + (size_t)warp * MDIM;
    float acc[NEXP];
#pragma unroll
    for (int e = 0; e < NEXP; e++) acc[e] = 0.f;
    for (int k = lane; k < MDIM; k += 32) {
        float xv = xr[k];
        const float* w = wg + k * NEXP;
#pragma unroll
        for (int e = 0; e < NEXP; e++) acc[e] += xv * w[e];
    }
#pragma unroll
    for (int e = 0; e < NEXP; e++) {
#pragma unroll
        for (int off = 16; off; off >>= 1)
            acc[e] += __shfl_xor_sync(0xffffffffu, acc[e], off);
    }
    if (lane == 0) {
        float mx = acc[0];
#pragma unroll
        for (int e = 1; e < NEXP; e++) mx = fmaxf(mx, acc[e]);
        float p[NEXP], sum = 0.f;
#pragma unroll
        for (int e = 0; e < NEXP; e++) { p[e] = expf(acc[e] - mx); sum += p[e]; }
        float inv = 1.f / sum;
        int e1 = 0; float b1 = p[0];
#pragma unroll
        for (int e = 1; e < NEXP; e++) if (p[e] > b1) { b1 = p[e]; e1 = e; }
        int e2 = 0; float b2 = -1.f;
#pragma unroll
        for (int e = 0; e < NEXP; e++)
            if (e != e1 && p[e] > b2) { b2 = p[e]; e2 = e; }
        g_e1[warp] = e1; g_e2[warp] = e2;
        g_gv1[warp] = b1 * inv; g_gv2[warp] = b2 * inv;
    }
}

// ---------------- 2) capacity scan: warp-ballot prefix (512 thr, 16 warps) ---
__global__ void scan_kernel(int G) {
    __shared__ int se1[SDIM];
    __shared__ int se2[SDIM];
    __shared__ int s_cnt1[NEXP];
    int g = blockIdx.x;
    int tid = threadIdx.x;
    int wid = tid >> 5, lane = tid & 31;
    int base = g * SDIM;
    if (g == 0) {                      // reset persistent queue each launch
        if (tid == 0) { g_work = 0; g_done2 = 0; }
        if (tid < NEXP) g_done[tid] = 0;
    }
    for (int s = tid; s < SDIM; s += blockDim.x) {
        se1[s] = g_e1[base + s];
        se2[s] = g_e2[base + s];
    }
    __syncthreads();
    // pass 1: expert = wid (16 warps = 16 experts)
    {
        int cnt = 0;
        for (int s0 = 0; s0 < SDIM; s0 += 32) {
            int e = se1[s0 + lane];
            unsigned mask = __ballot_sync(0xffffffffu, e == wid);
            if (e == wid) {
                int p = cnt + __popc(mask & ((1u << lane) - 1u));
                g_pos1[base + s0 + lane] = (p < CAP) ? p : -1;
            }
            cnt += __popc(mask);
        }
        if (lane == 0) s_cnt1[wid] = cnt < CAP ? cnt : CAP;
    }
    __syncthreads();
    // pass 2: second choices, offset by capacity-clipped first-choice count
    {
        int cnt = s_cnt1[wid];
        for (int s0 = 0; s0 < SDIM; s0 += 32) {
            int e = se2[s0 + lane];
            unsigned mask = __ballot_sync(0xffffffffu, e == wid);
            if (e == wid) {
                int p = cnt + __popc(mask & ((1u << lane) - 1u));
                g_pos2[base + s0 + lane] = (p < CAP) ? p : -1;
            }
            cnt += __popc(mask);
        }
    }
    __syncthreads();
    for (int s = tid; s < SDIM; s += blockDim.x) {
        int t = base + s;
        float a = (g_pos1[t] >= 0) ? g_gv1[t] : 0.f;
        float b = (g_pos2[t] >= 0) ? g_gv2[t] : 0.f;
        float den = a + b;
        den = (den > 0.f) ? den : 1.f;
        g_w1[t] = a / den;
        g_w2[t] = b / den;
    }
}

// ---------------- 3) scatter tokens into dispatch buffer (float4) ------------
__global__ void scatter_kernel(const float* __restrict__ x, int G) {
    int t = blockIdx.x;
    int g = t / SDIM;
    const float4* xr = (const float4*)(x + (size_t)t * MDIM);
    int p1 = g_pos1[t], p2 = g_pos2[t];
    float4* d1 = (p1 >= 0) ? (float4*)(g_disp + (((size_t)g_e1[t] * G + g) * CAP + p1) * MDIM) : nullptr;
    float4* d2 = (p2 >= 0) ? (float4*)(g_disp + (((size_t)g_e2[t] * G + g) * CAP + p2) * MDIM) : nullptr;
    int m = threadIdx.x;            // 192 threads = 192 float4 = 768 floats
    float4 v = xr[m];
    if (d1) d1[m] = v;
    if (d2) d2[m] = v;
}

// ---------------- SGEMM tile body (R12-proven, byte-identical) ---------------
__device__ void sgemm_tile(
    const float* __restrict__ A, const float* __restrict__ B, float* __restrict__ C,
    int K, int lda, int ldb, int ldc, bool relu, int bx, int by) {
    __shared__ float As[2][16][128];
    __shared__ float Bs[2][16][128];
    const int tid = threadIdx.x;
    const int arow = tid >> 1, acol = (tid & 1) * 8;   // A loader: 128 rows x 16 k
    const int brow = tid >> 4, bcol = (tid & 15) * 8;  // B loader: 16 k x 128 cols
    const int tx = tid & 15, ty = tid >> 4;            // 16x16 compute threads

    A += (size_t)by * 128 * lda;
    B += (size_t)bx * 128;
    C += (size_t)by * 128 * ldc + (size_t)bx * 128;

    const float* Arow = A + (size_t)arow * lda + acol;
    const float* Brow0 = B + (size_t)brow * ldb + bcol;

    const int nT = K / 16;

    float4 a0, a1, b0, b1;

    a0 = *(const float4*)(Arow);
    a1 = *(const float4*)(Arow + 4);
    b0 = *(const float4*)(Brow0);
    b1 = *(const float4*)(Brow0 + 4);
    {
        As[0][acol + 0][arow] = a0.x; As[0][acol + 1][arow] = a0.y;
        As[0][acol + 2][arow] = a0.z; As[0][acol + 3][arow] = a0.w;
        As[0][acol + 4][arow] = a1.x; As[0][acol + 5][arow] = a1.y;
        As[0][acol + 6][arow] = a1.z; As[0][acol + 7][arow] = a1.w;
        *(float4*)&Bs[0][brow][bcol]     = b0;
        *(float4*)&Bs[0][brow][bcol + 4] = b1;
    }
    __syncthreads();

    float acc[8][8];
#pragma unroll
    for (int i = 0; i < 8; i++)
#pragma unroll
        for (int j = 0; j < 8; j++) acc[i][j] = 0.f;

    for (int t = 0; t < nT; t++) {
        if (t + 1 < nT) {
            const float* An = Arow + (t + 1) * 16;
            const float* Bn = Brow0 + (size_t)(t + 1) * 16 * ldb;
            a0 = *(const float4*)(An);
            a1 = *(const float4*)(An + 4);
            b0 = *(const float4*)(Bn);
            b1 = *(const float4*)(Bn + 4);
        }

        const int s = t & 1;
#pragma unroll
        for (int k = 0; k < 16; k++) {
            float ar[8], br[8];
            *(float4*)&ar[0] = *(const float4*)&As[s][k][ty * 4];
            *(float4*)&ar[4] = *(const float4*)&As[s][k][64 + ty * 4];
            *(float4*)&br[0] = *(const float4*)&Bs[s][k][tx * 4];
            *(float4*)&br[4] = *(const float4*)&Bs[s][k][64 + tx * 4];
#pragma unroll
            for (int i = 0; i < 8; i++)
#pragma unroll
                for (int j = 0; j < 8; j++) acc[i][j] += ar[i] * br[j];
        }

        if (t + 1 < nT) {
            const int sn = (t + 1) & 1;
            As[sn][acol + 0][arow] = a0.x; As[sn][acol + 1][arow] = a0.y;
            As[sn][acol + 2][arow] = a0.z; As[sn][acol + 3][arow] = a0.w;
            As[sn][acol + 4][arow] = a1.x; As[sn][acol + 5][arow] = a1.y;
            As[sn][acol + 6][arow] = a1.z; As[sn][acol + 7][arow] = a1.w;
            *(float4*)&Bs[sn][brow][bcol]     = b0;
            *(float4*)&Bs[sn][brow][bcol + 4] = b1;
        }
        __syncthreads();
    }

#pragma unroll
    for (int ih = 0; ih < 2; ih++) {
#pragma unroll
        for (int i = 0; i < 4; i++) {
            int row = ih * 64 + ty * 4 + i;
            float* cr = C + (size_t)row * ldc;
#pragma unroll
            for (int jh = 0; jh < 2; jh++) {
                float4 v;
                v.x = acc[ih * 4 + i][jh * 4 + 0];
                v.y = acc[ih * 4 + i][jh * 4 + 1];
                v.z = acc[ih * 4 + i][jh * 4 + 2];
                v.w = acc[ih * 4 + i][jh * 4 + 3];
                if (relu) {
                    v.x = fmaxf(v.x, 0.f); v.y = fmaxf(v.y, 0.f);
                    v.z = fmaxf(v.z, 0.f); v.w = fmaxf(v.w, 0.f);
                }
                *(float4*)(cr + jh * 64 + tx * 4) = v;
            }
        }
    }
}

// ------- 4+5+6) persistent fused GEMM1 + GEMM2 + combine (work queue) --------
__global__ __launch_bounds__(256, 2) void moe_gemm_fused(
    const float* __restrict__ wi, const float* __restrict__ wo,
    float* __restrict__ out, int G, int T)
{
    __shared__ int s_id;
    const int Mr = G * CAP;                         // 512
    const int mT = Mr / 128;                        // 4
    const int t1_per_e = (HDIM / 128) * mT;         // 96
    const int nT1 = NEXP * t1_per_e;                // 1536
    const int t2_per_s = (MDIM / 128) * mT;         // 24
    const int t2_per_e = KSPLIT * t2_per_s;         // 96
    const int nT2 = NEXP * t2_per_e;                // 1536
    const int nComb = (T + 15) / 16;                // 256 combine tiles
    const int nAll = nT1 + nT2 + nComb;

    for (;;) {
        if (threadIdx.x == 0) s_id = atomicAdd(&g_work, 1);
        __syncthreads();
        int id = s_id;
        __syncthreads();
        if (id >= nAll) break;

        if (id < nT1) {
            // GEMM1 tile: h[e] = relu(disp[e] @ wi[e])
            int e = id / t1_per_e, r = id % t1_per_e;
            int n = r / mT, m = r % mT;
            const float* A = g_disp + (size_t)e * Mr * MDIM;
            const float* B = wi + (size_t)e * MDIM * HDIM;
            float* C = g_h + (size_t)e * Mr * HDIM;
            sgemm_tile(A, B, C, MDIM, MDIM, HDIM, HDIM, true, n, m);
            __syncthreads();
            if (threadIdx.x == 0) { __threadfence(); atomicAdd(&g_done[e], 1); }
        } else if (id < nT1 + nT2) {
            // GEMM2 tile (split-K): gated on expert e's gemm1 completion
            int id2 = id - nT1;
            int e = id2 / t2_per_e, r = id2 % t2_per_e;
            int s = r / t2_per_s, r2 = r % t2_per_s;
            int n = r2 / mT, m = r2 % mT;
            if (threadIdx.x == 0) {
                while (*(volatile int*)&g_done[e] < t1_per_e) __nanosleep(64);
            }
            __syncthreads();
            __threadfence();   // acquire: order g_h reads after observed flag
            const int KS = HDIM / KSPLIT;          // 768 per slice
            const float* A = g_h + (size_t)e * Mr * HDIM + (size_t)s * KS;
            const float* B = wo + (size_t)e * HDIM * MDIM + (size_t)s * KS * MDIM;
            float* C = g_eoP + ((size_t)s * NEXP + e) * Mr * MDIM;
            sgemm_tile(A, B, C, KS, HDIM, MDIM, MDIM, false, n, m);
            __syncthreads();
            if (threadIdx.x == 0) { __threadfence(); atomicAdd(&g_done2, 1); }
        } else {
            // combine tile: 16 tokens, gated on ALL gemm2 tiles done
            int cid = id - nT1 - nT2;
            if (threadIdx.x == 0) {
                while (*(volatile int*)&g_done2 < nT2) __nanosleep(64);
            }
            __syncthreads();
            __threadfence();   // acquire: order g_eoP reads after flag
            int tg = threadIdx.x >> 4, l16 = threadIdx.x & 15;   // 16 thr/token
            int t = cid * 16 + tg;
            if (t < T) {
                int g = t / SDIM;
                int p1 = g_pos1[t], p2 = g_pos2[t];
                float w1 = g_w1[t], w2 = g_w2[t];
                const size_t sliceStride4 = (size_t)NEXP * G * CAP * MDIM / 4;
                const float4* r1 = (p1 >= 0)
                    ? (const float4*)(g_eoP + (((size_t)g_e1[t] * G + g) * CAP + p1) * MDIM) : nullptr;
                const float4* r2 = (p2 >= 0)
                    ? (const float4*)(g_eoP + (((size_t)g_e2[t] * G + g) * CAP + p2) * MDIM) : nullptr;
                float4* o = (float4*)(out + (size_t)t * MDIM);
#pragma unroll
                for (int j = 0; j < 12; j++) {       // 12*16 = 192 float4 = 768
                    int m = l16 + j * 16;
                    float4 v; v.x = v.y = v.z = v.w = 0.f;
                    if (r1) {
                        float4 s1; s1.x = s1.y = s1.z = s1.w = 0.f;
#pragma unroll
                        for (int s = 0; s < KSPLIT; s++) {
                            float4 p = r1[s * sliceStride4 + m];
                            s1.x += p.x; s1.y += p.y; s1.z += p.z; s1.w += p.w;
                        }
                        v.x += w1 * s1.x; v.y += w1 * s1.y;
                        v.z += w1 * s1.z; v.w += w1 * s1.w;
                    }
                    if (r2) {
                        float4 s2; s2.x = s2.y = s2.z = s2.w = 0.f;
#pragma unroll
                        for (int s = 0; s < KSPLIT; s++) {
                            float4 p = r2[s * sliceStride4 + m];
                            s2.x += p.x; s2.y += p.y; s2.z += p.z; s2.w += p.w;
                        }
                        v.x += w2 * s2.x; v.y += w2 * s2.y;
                        v.z += w2 * s2.z; v.w += w2 * s2.w;
                    }
                    o[m] = v;
                }
            }
            __syncthreads();
        }
    }
}

// ---------------- launcher --------------------------------------------------
extern "C" void kernel_launch(void* const* d_in, const int* in_sizes, int n_in,
                              void* d_out, int out_size) {
    const float* x  = (const float*)d_in[0];   // [4,1024,768] fp32
    const float* wg = (const float*)d_in[1];   // [768,16]
    const float* wi = (const float*)d_in[2];   // [16,768,3072]
    const float* wo = (const float*)d_in[3];   // [16,3072,768]
    float* out = (float*)d_out;

    int T = in_sizes[0] / MDIM;   // 4096 tokens
    int G = T / SDIM;             // 2 groups
    if (G > GMAX) G = GMAX;

    int dev = 0, sms = 148;
    cudaGetDevice(&dev);
    cudaDeviceGetAttribute(&sms, cudaDevAttrMultiProcessorCount, dev);

    gating_kernel<<<(T + 3) / 4, 128>>>(x, wg, T);
    scan_kernel<<<G, 512>>>(G);
    scatter_kernel<<<T, 192>>>(x, G);
    moe_gemm_fused<<<2 * sms, 256>>>(wi, wo, out, G, T);
}